// round 2
// baseline (speedup 1.0000x reference)
#include <cuda_runtime.h>

// ============================================================================
// e3nn-style tensor product, uvw, MUL1=MULO=128, MUL2=1, l in {0,1,2}
// out[z, so+k, w] = sum_p sum_u A_p[z,k,u] * W_p[u,w]
//   A_p[z,k,u]    = sum_i c_p[z,i,k] * x1[z, s1+i, u]
//   c_p[z,i,k]    = sum_j w3j_p[i,j,k] * x2[z, s2+j]        (alpha folded in w3j)
// ============================================================================

#define NPATH 15
#define TZ 8

__constant__ int c_l1[NPATH] = {0,0,0,1,1,1,1,1,1,2,2,2,2,2,2};
__constant__ int c_l2[NPATH] = {0,1,2,0,1,1,1,2,2,0,1,1,2,2,2};
__constant__ int c_lo[NPATH] = {0,1,2,1,0,1,2,1,2,2,1,2,0,1,2};

// w3j (real basis, normalized, * alpha) per path, padded to [5][5][5]
__device__ float g_w3j[NPATH * 125];

// ---------------------------------------------------------------------------
// Setup: compute real-basis Wigner 3j exactly as the reference does (fp64)
// ---------------------------------------------------------------------------

__device__ __forceinline__ void qentry(int l, int r, int c, double& re, double& im) {
    // _change_basis_real_to_complex(l)[r][c], including (-1j)^l factor
    int m = r - l;
    const double s2 = 0.70710678118654752440;
    double a = 0.0, b = 0.0;
    if (m < 0) {
        if (c == l - m)      a = s2;    // col l+|m|
        else if (c == l + m) b = -s2;   // col l-|m|
    } else if (m == 0) {
        if (c == l) a = 1.0;
    } else {
        double sg = (m & 1) ? -1.0 : 1.0;
        if (c == l + m)      a = sg * s2;
        else if (c == l - m) b = sg * s2;
    }
    // multiply by (-i)^l
    switch (l & 3) {
        case 0: re = a;  im = b;  break;
        case 1: re = b;  im = -a; break;   // *( -i )
        case 2: re = -a; im = -b; break;   // *( -1 )
        default: re = -b; im = a; break;   // *(  i )
    }
}

__device__ double su2_cg(int j1, int m1, int j2, int m2, int j3, int m3) {
    if (m3 != m1 + m2) return 0.0;
    const double F[8] = {1.0, 1.0, 2.0, 6.0, 24.0, 120.0, 720.0, 5040.0};
    int vmin = -j1 + j2 + m3; if (-j1 + m1 > vmin) vmin = -j1 + m1; if (vmin < 0) vmin = 0;
    int vmax = j2 + j3 + m1; if (j3 - j1 + j2 < vmax) vmax = j3 - j1 + j2; if (j3 + m3 < vmax) vmax = j3 + m3;
    double C = sqrt((2.0 * j3 + 1.0)
                    * F[j3 + j1 - j2] * F[j3 - j1 + j2] * F[j1 + j2 - j3] / F[j1 + j2 + j3 + 1]
                    * F[j3 + m3] * F[j3 - m3]
                    / (F[j1 - m1] * F[j1 + m1] * F[j2 - m2] * F[j2 + m2]));
    double S = 0.0;
    for (int v = vmin; v <= vmax; v++) {
        double sgn = ((v + j2 + m2) & 1) ? -1.0 : 1.0;
        S += sgn / F[v] * F[j2 + j3 + m1 - v] * F[j1 - m1 + v]
             / (F[j3 - j1 + j2 - v] * F[j3 + m3 - v] * F[v + j1 - j2 - m3]);
    }
    return C * S;
}

__global__ void w3j_setup_kernel() {
    int p = blockIdx.x;
    int l1 = c_l1[p], l2 = c_l2[p], l3 = c_lo[p];
    int n1 = 2 * l1 + 1, n2 = 2 * l2 + 1, n3 = 2 * l3 + 1;
    int tid = threadIdx.x;
    int a = tid / 25, b = (tid / 5) % 5, cc = tid % 5;

    double val = 0.0;
    if (tid < 125 && a < n1 && b < n2 && cc < n3) {
        // out[a][b][cc] = Re sum_{i,k,n} Q1[i][a] Q2[k][b] conj(Q3[n][cc]) CG(...)
        for (int i = 0; i < n1; i++) {
            double q1r, q1i; qentry(l1, i, a, q1r, q1i);
            if (q1r == 0.0 && q1i == 0.0) continue;
            for (int k = 0; k < n2; k++) {
                double q2r, q2i; qentry(l2, k, b, q2r, q2i);
                if (q2r == 0.0 && q2i == 0.0) continue;
                double pr = q1r * q2r - q1i * q2i;
                double pi = q1r * q2i + q1i * q2r;
                for (int nn = 0; nn < n3; nn++) {
                    double q3r, q3i; qentry(l3, nn, cc, q3r, q3i);
                    if (q3r == 0.0 && q3i == 0.0) continue;
                    double cg = su2_cg(l1, i - l1, l2, k - l2, l3, nn - l3);
                    if (cg == 0.0) continue;
                    val += cg * (pr * q3r + pi * q3i);   // real part of q1*q2*conj(q3)
                }
            }
        }
    }

    __shared__ double red[128];
    red[tid] = val * val;
    __syncthreads();
    for (int s = 64; s > 0; s >>= 1) {
        if (tid < s) red[tid] += red[tid + s];
        __syncthreads();
    }
    double norm = sqrt(red[0]);

    // alpha: irrep 'component', path 'element' normalization.
    // num_elements(io) = 128 * (#paths with that io); counts are {3,6,6} for io=0,1,2
    const int iocnt[3] = {3, 6, 6};
    double alpha = sqrt((double)(2 * l3 + 1) / (128.0 * (double)iocnt[l3]));
    float outv = 0.0f;
    if (norm > 0.0) outv = (float)(val / norm * alpha);
    if (tid < 125) g_w3j[p * 125 + tid] = outv;
}

// ---------------------------------------------------------------------------
// Main fused kernel: per-block 8 samples; build A tile in smem, fp32 GEMM vs W
// ---------------------------------------------------------------------------

template <int LO>
__device__ __forceinline__ void gemm_acc(const float* __restrict__ Wp,
                                         const float* __restrict__ sAs,
                                         float acc[4][9], int w, int h) {
    constexpr int NK = 2 * LO + 1;
    constexpr int SO = (LO == 0) ? 0 : ((LO == 1) ? 1 : 4);
    const float* As0 = sAs + (h * 4) * 5 * 128;
#pragma unroll 2
    for (int u = 0; u < 128; u += 4) {
        float w0 = __ldg(Wp + (u + 0) * 128 + w);
        float w1 = __ldg(Wp + (u + 1) * 128 + w);
        float w2 = __ldg(Wp + (u + 2) * 128 + w);
        float w3 = __ldg(Wp + (u + 3) * 128 + w);
#pragma unroll
        for (int z = 0; z < 4; z++) {
#pragma unroll
            for (int k = 0; k < NK; k++) {
                float4 av = *reinterpret_cast<const float4*>(As0 + (z * 5 + k) * 128 + u);
                float s = acc[z][SO + k];
                s = fmaf(av.x, w0, s);
                s = fmaf(av.y, w1, s);
                s = fmaf(av.z, w2, s);
                s = fmaf(av.w, w3, s);
                acc[z][SO + k] = s;
            }
        }
    }
}

__global__ __launch_bounds__(256, 2)
void tp_main_kernel(const float* __restrict__ x1, const float* __restrict__ x2,
                    const float* __restrict__ wt, float* __restrict__ out, int n) {
    __shared__ __align__(16) float sAs[TZ * 5 * 128];  // A tile [z][k][u]
    __shared__ float sCs[TZ * 5 * 5];                  // c tile [z][i][k]

    const int t = threadIdx.x;
    const int w = t & 127;
    const int h = t >> 7;                 // z-half owner: h=0 -> z 0..3, h=1 -> z 4..7
    const long z0 = (long)blockIdx.x * TZ;

    float acc[4][9];
#pragma unroll
    for (int z = 0; z < 4; z++)
#pragma unroll
        for (int r = 0; r < 9; r++) acc[z][r] = 0.0f;

    for (int p = 0; p < NPATH; p++) {
        const int l1 = c_l1[p], l2 = c_l2[p], lo = c_lo[p];
        const int n1 = 2 * l1 + 1, n2 = 2 * l2 + 1, nk = 2 * lo + 1;
        const int s1 = (l1 == 0) ? 0 : ((l1 == 1) ? 1 : 4);
        const int s2 = (l2 == 0) ? 0 : ((l2 == 1) ? 1 : 4);

        // ---- c_p[z,i,k] = sum_j w3j[i,j,k] * x2[z, s2+j]
        const int tot = TZ * n1 * nk;
        if (t < tot) {
            int z = t / (n1 * nk);
            int r = t - z * (n1 * nk);
            int i = r / nk;
            int k = r - i * nk;
            float s = 0.0f;
            long zg = z0 + z;
            if (zg < n) {
                for (int j = 0; j < n2; j++)
                    s += g_w3j[p * 125 + (i * 5 + j) * 5 + k] * __ldg(&x2[zg * 9 + s2 + j]);
            }
            sCs[(z * 5 + i) * 5 + k] = s;
        }
        __syncthreads();   // cs ready; also fences previous path's gemm reads of sAs

        // ---- A_p[z,k,u] = sum_i c_p[z,i,k] * x1[z, s1+i, u]
        const int totA = TZ * nk * 128;
        for (int idx = t; idx < totA; idx += 256) {
            int u = idx & 127;
            int r = idx >> 7;
            int z = r / nk;
            int k = r - z * nk;
            float s = 0.0f;
            long zg = z0 + z;
            if (zg < n) {
                const float* x1r = x1 + zg * 1152 + (long)(s1)*128 + u;
                for (int i = 0; i < n1; i++)
                    s += sCs[(z * 5 + i) * 5 + k] * __ldg(x1r + i * 128);
            }
            sAs[(z * 5 + k) * 128 + u] = s;
        }
        __syncthreads();   // As ready for gemm

        // ---- accumulate A @ W_p into registers
        const float* Wp = wt + (long)p * 16384;
        switch (lo) {
            case 0: gemm_acc<0>(Wp, sAs, acc, w, h); break;
            case 1: gemm_acc<1>(Wp, sAs, acc, w, h); break;
            default: gemm_acc<2>(Wp, sAs, acc, w, h); break;
        }
        // no sync needed here; the sync after next path's cs-write fences sAs
    }

    // ---- write out (N, 9, 128); each half owns its 4 z values
#pragma unroll
    for (int z = 0; z < 4; z++) {
        long zg = z0 + h * 4 + z;
        if (zg < n) {
#pragma unroll
            for (int r = 0; r < 9; r++)
                out[zg * 1152 + r * 128 + w] = acc[z][r];
        }
    }
}

// ---------------------------------------------------------------------------

extern "C" void kernel_launch(void* const* d_in, const int* in_sizes, int n_in,
                              void* d_out, int out_size) {
    const float* x1 = (const float*)d_in[0];   // (N, 9, 128)
    const float* x2 = (const float*)d_in[1];   // (N, 9, 1)
    const float* wt = (const float*)d_in[2];   // (15 * 128 * 1 * 128,)
    float* out = (float*)d_out;                // (N, 9, 128)

    int n = in_sizes[0] / (9 * 128);

    w3j_setup_kernel<<<NPATH, 128>>>();

    int blocks = (n + TZ - 1) / TZ;
    tp_main_kernel<<<blocks, 256>>>(x1, x2, wt, out, n);
}

// round 3
// speedup vs baseline: 1.0490x; 1.0490x over previous
#include <cuda_runtime.h>

// ============================================================================
// e3nn-style tensor product, uvw, MUL1=MULO=128, MUL2=1, l in {0,1,2}
// out[z, so+k, w] = sum_p sum_u A_p[z,k,u] * W_p[u,w]
//   A_p[z,k,u]    = sum_i c_p[z,i,k] * x1[z, s1+i, u]
//   c_p[z,i,k]    = sum_j w3j_p[i,j,k] * x2[z, s2+j]        (alpha folded in w3j)
// ============================================================================

#define NPATH 15
#define TZ 8

__constant__ int c_l1[NPATH] = {0,0,0,1,1,1,1,1,1,2,2,2,2,2,2};
__constant__ int c_l2[NPATH] = {0,1,2,0,1,1,1,2,2,0,1,1,2,2,2};
__constant__ int c_lo[NPATH] = {0,1,2,1,0,1,2,1,2,2,1,2,0,1,2};

// w3j (real basis, normalized, * alpha) per path, padded to [5][5][5]
__device__ float g_w3j[NPATH * 125];

// ---------------------------------------------------------------------------
// Setup: compute real-basis Wigner 3j exactly as the reference does (fp64)
// ---------------------------------------------------------------------------

__device__ __forceinline__ void qentry(int l, int r, int c, double& re, double& im) {
    // _change_basis_real_to_complex(l)[r][c], including (-1j)^l factor
    int m = r - l;
    const double s2 = 0.70710678118654752440;
    double a = 0.0, b = 0.0;
    if (m < 0) {
        if (c == l - m)      a = s2;    // col l+|m|
        else if (c == l + m) b = -s2;   // col l-|m|
    } else if (m == 0) {
        if (c == l) a = 1.0;
    } else {
        double sg = (m & 1) ? -1.0 : 1.0;
        if (c == l + m)      a = sg * s2;
        else if (c == l - m) b = sg * s2;
    }
    // multiply by (-i)^l
    switch (l & 3) {
        case 0: re = a;  im = b;  break;
        case 1: re = b;  im = -a; break;   // *( -i )
        case 2: re = -a; im = -b; break;   // *( -1 )
        default: re = -b; im = a; break;   // *(  i )
    }
}

__device__ double su2_cg(int j1, int m1, int j2, int m2, int j3, int m3) {
    if (m3 != m1 + m2) return 0.0;
    const double F[8] = {1.0, 1.0, 2.0, 6.0, 24.0, 120.0, 720.0, 5040.0};
    int vmin = -j1 + j2 + m3; if (-j1 + m1 > vmin) vmin = -j1 + m1; if (vmin < 0) vmin = 0;
    int vmax = j2 + j3 + m1; if (j3 - j1 + j2 < vmax) vmax = j3 - j1 + j2; if (j3 + m3 < vmax) vmax = j3 + m3;
    double C = sqrt((2.0 * j3 + 1.0)
                    * F[j3 + j1 - j2] * F[j3 - j1 + j2] * F[j1 + j2 - j3] / F[j1 + j2 + j3 + 1]
                    * F[j3 + m3] * F[j3 - m3]
                    / (F[j1 - m1] * F[j1 + m1] * F[j2 - m2] * F[j2 + m2]));
    double S = 0.0;
    for (int v = vmin; v <= vmax; v++) {
        double sgn = ((v + j2 + m2) & 1) ? -1.0 : 1.0;
        S += sgn / F[v] * F[j2 + j3 + m1 - v] * F[j1 - m1 + v]
             / (F[j3 - j1 + j2 - v] * F[j3 + m3 - v] * F[v + j1 - j2 - m3]);
    }
    return C * S;
}

__global__ void w3j_setup_kernel() {
    int p = blockIdx.x;
    int l1 = c_l1[p], l2 = c_l2[p], l3 = c_lo[p];
    int n1 = 2 * l1 + 1, n2 = 2 * l2 + 1, n3 = 2 * l3 + 1;
    int tid = threadIdx.x;
    int a = tid / 25, b = (tid / 5) % 5, cc = tid % 5;

    double val = 0.0;
    if (tid < 125 && a < n1 && b < n2 && cc < n3) {
        // out[a][b][cc] = Re sum_{i,k,n} Q1[i][a] Q2[k][b] conj(Q3[n][cc]) CG(...)
        for (int i = 0; i < n1; i++) {
            double q1r, q1i; qentry(l1, i, a, q1r, q1i);
            if (q1r == 0.0 && q1i == 0.0) continue;
            for (int k = 0; k < n2; k++) {
                double q2r, q2i; qentry(l2, k, b, q2r, q2i);
                if (q2r == 0.0 && q2i == 0.0) continue;
                double pr = q1r * q2r - q1i * q2i;
                double pi = q1r * q2i + q1i * q2r;
                for (int nn = 0; nn < n3; nn++) {
                    double q3r, q3i; qentry(l3, nn, cc, q3r, q3i);
                    if (q3r == 0.0 && q3i == 0.0) continue;
                    double cg = su2_cg(l1, i - l1, l2, k - l2, l3, nn - l3);
                    if (cg == 0.0) continue;
                    val += cg * (pr * q3r + pi * q3i);   // real part of q1*q2*conj(q3)
                }
            }
        }
    }

    __shared__ double red[128];
    red[tid] = val * val;
    __syncthreads();
    for (int s = 64; s > 0; s >>= 1) {
        if (tid < s) red[tid] += red[tid + s];
        __syncthreads();
    }
    double norm = sqrt(red[0]);

    // alpha: irrep 'component', path 'element' normalization.
    // num_elements(io) = 128 * (#paths with that io); counts are {3,6,6} for io=0,1,2
    const int iocnt[3] = {3, 6, 6};
    double alpha = sqrt((double)(2 * l3 + 1) / (128.0 * (double)iocnt[l3]));
    float outv = 0.0f;
    if (norm > 0.0) outv = (float)(val / norm * alpha);
    if (tid < 125) g_w3j[p * 125 + tid] = outv;
}

// ---------------------------------------------------------------------------
// Main fused kernel: per-block 8 samples; build A tile in smem, fp32 GEMM vs W
// ---------------------------------------------------------------------------

template <int LO>
__device__ __forceinline__ void gemm_acc(const float* __restrict__ Wp,
                                         const float* __restrict__ sAs,
                                         float acc[4][9], int w, int h) {
    constexpr int NK = 2 * LO + 1;
    constexpr int SO = (LO == 0) ? 0 : ((LO == 1) ? 1 : 4);
    const float* As0 = sAs + (h * 4) * 5 * 128;
#pragma unroll 2
    for (int u = 0; u < 128; u += 4) {
        float w0 = __ldg(Wp + (u + 0) * 128 + w);
        float w1 = __ldg(Wp + (u + 1) * 128 + w);
        float w2 = __ldg(Wp + (u + 2) * 128 + w);
        float w3 = __ldg(Wp + (u + 3) * 128 + w);
#pragma unroll
        for (int z = 0; z < 4; z++) {
#pragma unroll
            for (int k = 0; k < NK; k++) {
                float4 av = *reinterpret_cast<const float4*>(As0 + (z * 5 + k) * 128 + u);
                float s = acc[z][SO + k];
                s = fmaf(av.x, w0, s);
                s = fmaf(av.y, w1, s);
                s = fmaf(av.z, w2, s);
                s = fmaf(av.w, w3, s);
                acc[z][SO + k] = s;
            }
        }
    }
}

__global__ __launch_bounds__(256, 2)
void tp_main_kernel(const float* __restrict__ x1, const float* __restrict__ x2,
                    const float* __restrict__ wt, float* __restrict__ out, int n) {
    __shared__ __align__(16) float sAs[TZ * 5 * 128];  // A tile [z][k][u]
    __shared__ float sCs[TZ * 5 * 5];                  // c tile [z][i][k]

    const int t = threadIdx.x;
    const int w = t & 127;
    const int h = t >> 7;                 // z-half owner: h=0 -> z 0..3, h=1 -> z 4..7
    const long z0 = (long)blockIdx.x * TZ;

    float acc[4][9];
#pragma unroll
    for (int z = 0; z < 4; z++)
#pragma unroll
        for (int r = 0; r < 9; r++) acc[z][r] = 0.0f;

    for (int p = 0; p < NPATH; p++) {
        const int l1 = c_l1[p], l2 = c_l2[p], lo = c_lo[p];
        const int n1 = 2 * l1 + 1, n2 = 2 * l2 + 1, nk = 2 * lo + 1;
        const int s1 = (l1 == 0) ? 0 : ((l1 == 1) ? 1 : 4);
        const int s2 = (l2 == 0) ? 0 : ((l2 == 1) ? 1 : 4);

        // ---- c_p[z,i,k] = sum_j w3j[i,j,k] * x2[z, s2+j]
        const int tot = TZ * n1 * nk;
        if (t < tot) {
            int z = t / (n1 * nk);
            int r = t - z * (n1 * nk);
            int i = r / nk;
            int k = r - i * nk;
            float s = 0.0f;
            long zg = z0 + z;
            if (zg < n) {
                for (int j = 0; j < n2; j++)
                    s += g_w3j[p * 125 + (i * 5 + j) * 5 + k] * __ldg(&x2[zg * 9 + s2 + j]);
            }
            sCs[(z * 5 + i) * 5 + k] = s;
        }
        __syncthreads();   // cs ready; also fences previous path's gemm reads of sAs

        // ---- A_p[z,k,u] = sum_i c_p[z,i,k] * x1[z, s1+i, u]
        const int totA = TZ * nk * 128;
        for (int idx = t; idx < totA; idx += 256) {
            int u = idx & 127;
            int r = idx >> 7;
            int z = r / nk;
            int k = r - z * nk;
            float s = 0.0f;
            long zg = z0 + z;
            if (zg < n) {
                const float* x1r = x1 + zg * 1152 + (long)(s1)*128 + u;
                for (int i = 0; i < n1; i++)
                    s += sCs[(z * 5 + i) * 5 + k] * __ldg(x1r + i * 128);
            }
            sAs[(z * 5 + k) * 128 + u] = s;
        }
        __syncthreads();   // As ready for gemm

        // ---- accumulate A @ W_p into registers
        const float* Wp = wt + (long)p * 16384;
        switch (lo) {
            case 0: gemm_acc<0>(Wp, sAs, acc, w, h); break;
            case 1: gemm_acc<1>(Wp, sAs, acc, w, h); break;
            default: gemm_acc<2>(Wp, sAs, acc, w, h); break;
        }
        // no sync needed here; the sync after next path's cs-write fences sAs
    }

    // ---- write out (N, 9, 128); each half owns its 4 z values
#pragma unroll
    for (int z = 0; z < 4; z++) {
        long zg = z0 + h * 4 + z;
        if (zg < n) {
#pragma unroll
            for (int r = 0; r < 9; r++)
                out[zg * 1152 + r * 128 + w] = acc[z][r];
        }
    }
}

// ---------------------------------------------------------------------------

extern "C" void kernel_launch(void* const* d_in, const int* in_sizes, int n_in,
                              void* d_out, int out_size) {
    const float* x1 = (const float*)d_in[0];   // (N, 9, 128)
    const float* x2 = (const float*)d_in[1];   // (N, 9, 1)
    const float* wt = (const float*)d_in[2];   // (15 * 128 * 1 * 128,)
    float* out = (float*)d_out;                // (N, 9, 128)

    int n = in_sizes[0] / (9 * 128);

    w3j_setup_kernel<<<NPATH, 128>>>();

    int blocks = (n + TZ - 1) / TZ;
    tp_main_kernel<<<blocks, 256>>>(x1, x2, wt, out, n);
}

// round 5
// speedup vs baseline: 2.4491x; 2.3346x over previous
#include <cuda_runtime.h>
#include <cuda_bf16.h>
#include <cstdint>

#define NPATH 15
#define NENT 33

__constant__ int c_l1[NPATH] = {0,0,0,1,1,1,1,1,1,2,2,2,2,2,2};
__constant__ int c_l2[NPATH] = {0,1,2,0,1,1,1,2,2,0,1,1,2,2,2};
__constant__ int c_lo[NPATH] = {0,1,2,1,0,1,2,1,2,2,1,2,0,1,2};

// schedule: 5 passes over ko slots {0,1},{2,3},{4,5},{6,7},{8}
__constant__ int S_path[NENT] = {0,4,12,1,3,5,7,10,13, 1,3,5,7,10,13, 2,6,8,9,11,14, 2,6,8,9,11,14, 2,6,8,9,11,14};
__constant__ int S_k0[NENT]   = {0,0,0, 0,0,0,0,0,0,   1,1,1,1,1,1,   0,0,0,0,0,0,   2,2,2,2,2,2,   4,4,4,4,4,4};
__constant__ int S_nk[NENT]   = {1,1,1, 1,1,1,1,1,1,   2,2,2,2,2,2,   2,2,2,2,2,2,   2,2,2,2,2,2,   1,1,1,1,1,1};
__constant__ int S_slot[NENT] = {0,0,0, 1,1,1,1,1,1,   0,0,0,0,0,0,   0,0,0,0,0,0,   0,0,0,0,0,0,   0,0,0,0,0,0};
__constant__ int P_end[5] = {9,15,21,27,33};
__constant__ int P_kob[5] = {0,2,4,6,8};
__constant__ int P_ns[5]  = {2,2,2,2,1};

__device__ float g_w3j[NPATH * 125];
__device__ __nv_bfloat16 g_Wh[NPATH * 16384];   // swizzled [u-row 256B]
__device__ __nv_bfloat16 g_Wl[NPATH * 16384];

// smem layout (dynamic)
#define SO_X2 0
#define SO_SC 4608
#define SO_W  12288
#define SO_A0 77824
#define SO_A1 143360
#define SMEM_BYTES 208896

// ---------------- w3j setup (validated rounds 2-3) ----------------
__device__ __forceinline__ void qentry(int l, int r, int c, double& re, double& im) {
    int m = r - l;
    const double s2 = 0.70710678118654752440;
    double a = 0.0, b = 0.0;
    if (m < 0) {
        if (c == l - m)      a = s2;
        else if (c == l + m) b = -s2;
    } else if (m == 0) {
        if (c == l) a = 1.0;
    } else {
        double sg = (m & 1) ? -1.0 : 1.0;
        if (c == l + m)      a = sg * s2;
        else if (c == l - m) b = sg * s2;
    }
    switch (l & 3) {
        case 0: re = a;  im = b;  break;
        case 1: re = b;  im = -a; break;
        case 2: re = -a; im = -b; break;
        default: re = -b; im = a; break;
    }
}

__device__ double su2_cg(int j1, int m1, int j2, int m2, int j3, int m3) {
    if (m3 != m1 + m2) return 0.0;
    const double F[8] = {1.0, 1.0, 2.0, 6.0, 24.0, 120.0, 720.0, 5040.0};
    int vmin = -j1 + j2 + m3; if (-j1 + m1 > vmin) vmin = -j1 + m1; if (vmin < 0) vmin = 0;
    int vmax = j2 + j3 + m1; if (j3 - j1 + j2 < vmax) vmax = j3 - j1 + j2; if (j3 + m3 < vmax) vmax = j3 + m3;
    double C = sqrt((2.0 * j3 + 1.0)
                    * F[j3 + j1 - j2] * F[j3 - j1 + j2] * F[j1 + j2 - j3] / F[j1 + j2 + j3 + 1]
                    * F[j3 + m3] * F[j3 - m3]
                    / (F[j1 - m1] * F[j1 + m1] * F[j2 - m2] * F[j2 + m2]));
    double S = 0.0;
    for (int v = vmin; v <= vmax; v++) {
        double sgn = ((v + j2 + m2) & 1) ? -1.0 : 1.0;
        S += sgn / F[v] * F[j2 + j3 + m1 - v] * F[j1 - m1 + v]
             / (F[j3 - j1 + j2 - v] * F[j3 + m3 - v] * F[v + j1 - j2 - m3]);
    }
    return C * S;
}

__global__ void w3j_setup_kernel() {
    int p = blockIdx.x;
    int l1 = c_l1[p], l2 = c_l2[p], l3 = c_lo[p];
    int n1 = 2 * l1 + 1, n2 = 2 * l2 + 1, n3 = 2 * l3 + 1;
    int tid = threadIdx.x;
    int a = tid / 25, b = (tid / 5) % 5, cc = tid % 5;

    double val = 0.0;
    if (tid < 125 && a < n1 && b < n2 && cc < n3) {
        for (int i = 0; i < n1; i++) {
            double q1r, q1i; qentry(l1, i, a, q1r, q1i);
            if (q1r == 0.0 && q1i == 0.0) continue;
            for (int k = 0; k < n2; k++) {
                double q2r, q2i; qentry(l2, k, b, q2r, q2i);
                if (q2r == 0.0 && q2i == 0.0) continue;
                double pr = q1r * q2r - q1i * q2i;
                double pi = q1r * q2i + q1i * q2r;
                for (int nn = 0; nn < n3; nn++) {
                    double q3r, q3i; qentry(l3, nn, cc, q3r, q3i);
                    if (q3r == 0.0 && q3i == 0.0) continue;
                    double cg = su2_cg(l1, i - l1, l2, k - l2, l3, nn - l3);
                    if (cg == 0.0) continue;
                    val += cg * (pr * q3r + pi * q3i);
                }
            }
        }
    }

    __shared__ double red[128];
    red[tid] = val * val;
    __syncthreads();
    for (int s = 64; s > 0; s >>= 1) {
        if (tid < s) red[tid] += red[tid + s];
        __syncthreads();
    }
    double norm = sqrt(red[0]);
    const int iocnt[3] = {3, 6, 6};
    double alpha = sqrt((double)(2 * l3 + 1) / (128.0 * (double)iocnt[l3]));
    float outv = 0.0f;
    if (norm > 0.0) outv = (float)(val / norm * alpha);
    if (tid < 125) g_w3j[p * 125 + tid] = outv;
}

// ---------------- W split + swizzle prep ----------------
// layout: row u (256B = 128 w bf16), 16B granule g swizzled: g' = (w>>3) ^ (u&7)
__global__ void wprep_kernel(const float* __restrict__ wt) {
    int p = blockIdx.x;
    for (int idx = threadIdx.x; idx < 16384; idx += 256) {
        int u = idx >> 7, w = idx & 127;
        float v = wt[p * 16384 + idx];                     // wt[p][u][w]
        __nv_bfloat16 h = __float2bfloat16(v);
        __nv_bfloat16 l = __float2bfloat16(v - __bfloat162float(h));
        uint32_t off = (uint32_t)(u * 256 + (((w >> 3) ^ (u & 7)) << 4) + (w & 7) * 2);
        *(__nv_bfloat16*)((char*)g_Wh + p * 32768 + off) = h;
        *(__nv_bfloat16*)((char*)g_Wl + p * 32768 + off) = l;
    }
}

// ---------------- mma helpers ----------------
__device__ __forceinline__ uint32_t smem_u32(const void* p) {
    uint32_t a;
    asm("{ .reg .u64 t; cvta.to.shared.u64 t, %1; cvt.u32.u64 %0, t; }" : "=r"(a) : "l"(p));
    return a;
}
__device__ __forceinline__ void ldsm_x4(uint32_t* r, uint32_t a) {
    asm volatile("ldmatrix.sync.aligned.m8n8.x4.shared.b16 {%0,%1,%2,%3}, [%4];"
                 : "=r"(r[0]), "=r"(r[1]), "=r"(r[2]), "=r"(r[3]) : "r"(a));
}
__device__ __forceinline__ void ldsm_x2t(uint32_t* r, uint32_t a) {
    asm volatile("ldmatrix.sync.aligned.m8n8.x2.trans.shared.b16 {%0,%1}, [%2];"
                 : "=r"(r[0]), "=r"(r[1]) : "r"(a));
}
__device__ __forceinline__ void mma16816(float (&d)[4], const uint32_t* a, const uint32_t* b) {
    asm volatile("mma.sync.aligned.m16n8k16.row.col.f32.bf16.bf16.f32 "
                 "{%0,%1,%2,%3}, {%4,%5,%6,%7}, {%8,%9}, {%0,%1,%2,%3};"
                 : "+f"(d[0]), "+f"(d[1]), "+f"(d[2]), "+f"(d[3])
                 : "r"(a[0]), "r"(a[1]), "r"(a[2]), "r"(a[3]), "r"(b[0]), "r"(b[1]));
}

__device__ __forceinline__ void mma_phase(uint32_t Ab, uint32_t Wb,
                                          float (&acc)[16][4], int lane, int zb) {
#pragma unroll
    for (int kk = 0; kk < 8; kk++) {
        int m = lane >> 3, r = lane & 7;
        int row = zb + r + (m & 1) * 8;
        int gc = kk * 2 + (m >> 1);
        uint32_t ah[4], al[4];
        uint32_t aaddr = Ab + (uint32_t)(row * 256 + ((gc ^ (row & 7)) << 4));
        ldsm_x4(ah, aaddr);
        ldsm_x4(al, aaddr + 32768u);
        int brow = kk * 16 + (lane & 15);
        uint32_t bbase = Wb + (uint32_t)(brow * 256);
        int bx = brow & 7;
#pragma unroll
        for (int nt = 0; nt < 16; nt++) {
            uint32_t bh[2], bl[2];
            uint32_t baddr = bbase + (uint32_t)(((nt ^ bx)) << 4);
            ldsm_x2t(bh, baddr);
            ldsm_x2t(bl, baddr + 32768u);
            mma16816(acc[nt], ah, bh);
            mma16816(acc[nt], ah, bl);
            mma16816(acc[nt], al, bh);
        }
    }
}

__device__ __forceinline__ void store_acc(float (&acc)[16][4], float* __restrict__ out,
                                          int ko, int z0, int wid, int lane, int n) {
    int r0 = z0 + wid * 16 + (lane >> 2);
    int col = (lane & 3) * 2;
#pragma unroll
    for (int nt = 0; nt < 16; nt++) {
        if (r0 < n)
            *(float2*)(out + (long)r0 * 1152 + ko * 128 + nt * 8 + col) =
                make_float2(acc[nt][0], acc[nt][1]);
        if (r0 + 8 < n)
            *(float2*)(out + (long)(r0 + 8) * 1152 + ko * 128 + nt * 8 + col) =
                make_float2(acc[nt][2], acc[nt][3]);
        acc[nt][0] = acc[nt][1] = acc[nt][2] = acc[nt][3] = 0.0f;
    }
}

// ---------------- main kernel ----------------
__global__ __launch_bounds__(256, 1)
void tp_mma_kernel(const float* __restrict__ x1, const float* __restrict__ x2,
                   float* __restrict__ out, int n) {
    extern __shared__ __align__(1024) char smem[];
    uint32_t sb = smem_u32(smem);
    const int t = threadIdx.x;
    const int wid = t >> 5, lane = t & 31;
    const int z0 = blockIdx.x * 128;
    const int zb = wid * 16;

    float* sX2 = (float*)(smem + SO_X2);
    float* sC  = (float*)(smem + SO_SC);

    for (int idx = t; idx < 1152; idx += 256) {
        int z = idx / 9, j = idx - z * 9;
        int zg = z0 + z;
        sX2[idx] = (zg < n) ? x2[(long)zg * 9 + j] : 0.0f;
    }

    float acc0[16][4], acc1[16][4];
#pragma unroll
    for (int nt = 0; nt < 16; nt++)
#pragma unroll
        for (int j = 0; j < 4; j++) { acc0[nt][j] = 0.0f; acc1[nt][j] = 0.0f; }

    int pass = 0;

    for (int e = 0; e < NENT; e++) {
        const int p = S_path[e], k0 = S_k0[e], nk = S_nk[e], sl = S_slot[e];
        const int l1 = c_l1[p], l2 = c_l2[p];
        const int n1 = 2 * l1 + 1, n2 = 2 * l2 + 1;
        const int s1 = l1 * l1, s2 = l2 * l2;

        __syncthreads();   // prior MMA reads done before overwriting W/A/sC

        // stage W_p hi/lo (layout preserved)
        {
            const uint4* srcH = (const uint4*)(g_Wh + p * 16384);
            const uint4* srcL = (const uint4*)(g_Wl + p * 16384);
            uint4* dH = (uint4*)(smem + SO_W);
            uint4* dL = (uint4*)(smem + SO_W + 32768);
            for (int i = t; i < 2048; i += 256) { dH[i] = srcH[i]; dL[i] = srcL[i]; }
        }

        // c[z][i][kq]
        if (t < 128) {
            for (int i = 0; i < n1; i++)
                for (int kq = 0; kq < nk; kq++) {
                    int k = k0 + kq;
                    float s = 0.0f;
                    for (int j = 0; j < n2; j++)
                        s += g_w3j[p * 125 + (i * 5 + j) * 5 + k] * sX2[t * 9 + s2 + j];
                    sC[t * 12 + i * 2 + kq] = s;
                }
        }
        __syncthreads();

        // build A tiles (bf16 hi/lo, swizzled)
        for (int idx = t; idx < 8192; idx += 256) {
            int z = idx >> 6, u2 = idx & 63;
            long zg = z0 + z;
            float2 xv[5];
            const float* xr = x1 + zg * 1152 + s1 * 128 + u2 * 2;
#pragma unroll
            for (int i = 0; i < 5; i++) {
                if (i < n1 && zg < n) xv[i] = *(const float2*)(xr + i * 128);
                else { xv[i].x = 0.0f; xv[i].y = 0.0f; }
            }
            uint32_t boff = (uint32_t)(z * 256 + (((u2 >> 2) ^ (z & 7)) << 4) + (u2 & 3) * 4);
            for (int kq = 0; kq < nk; kq++) {
                float a0 = 0.0f, a1 = 0.0f;
#pragma unroll
                for (int i = 0; i < 5; i++) {
                    if (i < n1) {
                        float c = sC[z * 12 + i * 2 + kq];
                        a0 = fmaf(c, xv[i].x, a0);
                        a1 = fmaf(c, xv[i].y, a1);
                    }
                }
                __nv_bfloat162 hp, lp;
                hp.x = __float2bfloat16(a0);
                hp.y = __float2bfloat16(a1);
                lp.x = __float2bfloat16(a0 - __bfloat162float(hp.x));
                lp.y = __float2bfloat16(a1 - __bfloat162float(hp.y));
                char* base = smem + (kq ? SO_A1 : SO_A0) + boff;
                *(uint32_t*)base = *(uint32_t*)&hp;
                *(uint32_t*)(base + 32768) = *(uint32_t*)&lp;
            }
        }
        __syncthreads();

        // MMA
        uint32_t Wb = sb + SO_W;
        if (nk == 1) {
            if (sl == 0) mma_phase(sb + SO_A0, Wb, acc0, lane, zb);
            else         mma_phase(sb + SO_A0, Wb, acc1, lane, zb);
        } else {
            mma_phase(sb + SO_A0, Wb, acc0, lane, zb);
            mma_phase(sb + SO_A1, Wb, acc1, lane, zb);
        }

        // pass epilogue
        if (e == P_end[pass] - 1) {
            int kob = P_kob[pass], ns = P_ns[pass];
            store_acc(acc0, out, kob, z0, wid, lane, n);
            if (ns == 2) store_acc(acc1, out, kob + 1, z0, wid, lane, n);
            pass++;
        }
    }
}

// ---------------------------------------------------------------------------

extern "C" void kernel_launch(void* const* d_in, const int* in_sizes, int n_in,
                              void* d_out, int out_size) {
    const float* x1 = (const float*)d_in[0];   // (N, 9, 128)
    const float* x2 = (const float*)d_in[1];   // (N, 9, 1)
    const float* wt = (const float*)d_in[2];   // (15*128*128,)
    float* out = (float*)d_out;                // (N, 9, 128)

    int n = in_sizes[0] / 1152;

    w3j_setup_kernel<<<NPATH, 128>>>();
    wprep_kernel<<<NPATH, 256>>>(wt);

    cudaFuncSetAttribute(tp_mma_kernel, cudaFuncAttributeMaxDynamicSharedMemorySize, SMEM_BYTES);
    tp_mma_kernel<<<(n + 127) / 128, 256, SMEM_BYTES>>>(x1, x2, out, n);
}